// round 6
// baseline (speedup 1.0000x reference)
#include <cuda_runtime.h>

// Problem shape (fixed by reference setup_inputs): [B=64, S=2048, D=512] fp32
constexpr int B = 64;
constexpr int S = 2048;
constexpr int D = 512;
constexpr int D4 = D / 4;                      // 128 float4 per row
constexpr int CHUNK = 16;                      // timesteps per warp
constexpr int CHUNKS_PER_SEQ = S / CHUNK;      // 128
constexpr int THREADS = 256;                   // 8 warps/block (measured best shape)
constexpr int WARPS_PER_BLOCK = THREADS / 32;
constexpr int TOTAL_WARPS = B * CHUNKS_PER_SEQ;       // 8192
constexpr int GRID1 = TOTAL_WARPS / WARPS_PER_BLOCK;  // 1024 blocks

// Kernel 1: unnormalized squared L2 of consecutive-row diffs.
// Software-pipelined: row s+1's loads are issued BEFORE row s's diff/reduce/store,
// so 4 LDG.128 are always in flight while the FMA + shuffle chain runs.
// No atomics, no extra device globals (R3/R4: atomicMax tail cost ~9us).
__global__ void __launch_bounds__(THREADS)
l2_diff_kernel(const float4* __restrict__ x, float* __restrict__ out) {
    const int warp = (blockIdx.x * THREADS + threadIdx.x) >> 5;
    const int lane = threadIdx.x & 31;
    const int b    = warp / CHUNKS_PER_SEQ;
    const int s0   = (warp % CHUNKS_PER_SEQ) * CHUNK;

    const float4* base = x + (size_t)b * S * D4;
    float* orow = out + (size_t)b * S;

    // previous row: s0-1, except the very first chunk where d[0] = 0
    const int sprev   = (s0 == 0) ? 0 : (s0 - 1);
    const int s_start = (s0 == 0) ? 1 : s0;
    const int s_end   = s0 + CHUNK;

    if (s0 == 0 && lane == 0) orow[0] = 0.0f;

    float4 prev[4], cur[4], nxt[4];

    const float4* rp = base + (size_t)sprev * D4 + lane;
    #pragma unroll
    for (int j = 0; j < 4; ++j) prev[j] = rp[32 * j];

    const float4* rc = base + (size_t)s_start * D4 + lane;
    #pragma unroll
    for (int j = 0; j < 4; ++j) cur[j] = rc[32 * j];

    for (int s = s_start; s < s_end; ++s) {
        // prefetch row s+1 first (loads in flight during compute below)
        if (s + 1 < s_end) {
            const float4* rn = base + (size_t)(s + 1) * D4 + lane;
            #pragma unroll
            for (int j = 0; j < 4; ++j) nxt[j] = rn[32 * j];
        }

        float sum = 0.0f;
        #pragma unroll
        for (int j = 0; j < 4; ++j) {
            float dx = cur[j].x - prev[j].x;
            float dy = cur[j].y - prev[j].y;
            float dz = cur[j].z - prev[j].z;
            float dw = cur[j].w - prev[j].w;
            sum += dx * dx + dy * dy + dz * dz + dw * dw;
        }
        // warp reduce (sum over D)
        #pragma unroll
        for (int off = 16; off > 0; off >>= 1)
            sum += __shfl_xor_sync(0xffffffffu, sum, off);
        if (lane == 0) orow[s] = sum;

        #pragma unroll
        for (int j = 0; j < 4; ++j) { prev[j] = cur[j]; cur[j] = nxt[j]; }
    }
}

// Kernel 2: fused max+scale, one block per batch, single pass (R5 version).
constexpr int NTHREADS2 = 512;                 // = S/4 float4 per row
constexpr int NWARPS2 = NTHREADS2 / 32;        // 16

__global__ void __launch_bounds__(NTHREADS2)
normalize_kernel(float4* __restrict__ out) {
    const int b = blockIdx.x;
    float4* row = out + (size_t)b * (S / 4);

    float4 v = row[threadIdx.x];
    float m = fmaxf(fmaxf(v.x, v.y), fmaxf(v.z, v.w));

    #pragma unroll
    for (int off = 16; off > 0; off >>= 1)
        m = fmaxf(m, __shfl_xor_sync(0xffffffffu, m, off));

    __shared__ float s_wmax[NWARPS2];
    __shared__ float s_inv;
    const int wid = threadIdx.x >> 5;
    const int lid = threadIdx.x & 31;
    if (lid == 0) s_wmax[wid] = m;
    __syncthreads();

    if (threadIdx.x < 32) {
        float t = (threadIdx.x < NWARPS2) ? s_wmax[threadIdx.x] : 0.0f;
        #pragma unroll
        for (int off = 8; off > 0; off >>= 1)
            t = fmaxf(t, __shfl_xor_sync(0xffffffffu, t, off));
        if (threadIdx.x == 0) s_inv = 1.0f / t;
    }
    __syncthreads();

    const float inv = s_inv;
    v.x *= inv; v.y *= inv; v.z *= inv; v.w *= inv;
    row[threadIdx.x] = v;
}

extern "C" void kernel_launch(void* const* d_in, const int* in_sizes, int n_in,
                              void* d_out, int out_size) {
    const float4* x = (const float4*)d_in[0];
    (void)in_sizes; (void)n_in; (void)out_size;

    l2_diff_kernel<<<GRID1, THREADS>>>(x, (float*)d_out);
    normalize_kernel<<<B, NTHREADS2>>>((float4*)d_out);
}

// round 7
// speedup vs baseline: 1.0220x; 1.0220x over previous
#include <cuda_runtime.h>

// Problem shape (fixed by reference setup_inputs): [B=64, S=2048, D=512] fp32
constexpr int B = 64;
constexpr int S = 2048;
constexpr int D = 512;
constexpr int D4 = D / 4;                      // 128 float4 per row
constexpr int CHUNK = 16;                      // timesteps per warp
constexpr int THREADS = 256;                   // 8 warps/block (measured best shape)
constexpr int WARPS_PER_BLOCK = THREADS / 32;  // 8
constexpr int ROWS_PER_BLOCK = WARPS_PER_BLOCK * CHUNK;       // 128
constexpr int BLOCKS_PER_BATCH = S / ROWS_PER_BLOCK;          // 16
constexpr int GRID1 = B * BLOCKS_PER_BATCH;                   // 1024 blocks

// Kernel 1: unnormalized squared L2 of consecutive-row diffs.
// Block = 128 consecutive rows of one batch. Each warp parks its LAST row in
// smem so the next warp gets its boundary row without a global re-read:
// re-read overhead drops from 17/16 to 129/128 (272 MB -> 258 MB).
// No atomics (R3/R4: device-atomic tail cost ~9us).
__global__ void __launch_bounds__(THREADS)
l2_diff_kernel(const float4* __restrict__ x, float* __restrict__ out) {
    __shared__ float4 s_bound[WARPS_PER_BLOCK * 128];  // 8 rows x 512 floats = 16KB

    const int b    = blockIdx.x / BLOCKS_PER_BATCH;
    const int r0   = (blockIdx.x % BLOCKS_PER_BATCH) * ROWS_PER_BLOCK;
    const int w    = threadIdx.x >> 5;
    const int lane = threadIdx.x & 31;
    const int s0   = r0 + w * CHUNK;

    const float4* base = x + (size_t)b * S * D4;
    float* orow = out + (size_t)b * S;

    // Phase 1: load my chunk's LAST row; share it with warp w+1 via smem.
    float4 last[4];
    {
        const float4* rl = base + (size_t)(s0 + CHUNK - 1) * D4 + lane;
        #pragma unroll
        for (int j = 0; j < 4; ++j) last[j] = rl[32 * j];
        float4* sm = s_bound + w * 128 + lane;
        #pragma unroll
        for (int j = 0; j < 4; ++j) sm[32 * j] = last[j];
    }

    // Warp 0 also loads the block's global boundary row (independent of sync).
    float4 prev[4];
    const bool first_chunk = (r0 == 0) && (w == 0);
    if (w == 0) {
        const int sprev = (r0 == 0) ? 0 : (r0 - 1);
        const float4* rp = base + (size_t)sprev * D4 + lane;
        #pragma unroll
        for (int j = 0; j < 4; ++j) prev[j] = rp[32 * j];
    }

    __syncthreads();

    if (w != 0) {
        const float4* sp = s_bound + (w - 1) * 128 + lane;
        #pragma unroll
        for (int j = 0; j < 4; ++j) prev[j] = sp[32 * j];
    }

    if (first_chunk && lane == 0) orow[0] = 0.0f;

    const int s_start = first_chunk ? 1 : s0;
    const int s_last  = s0 + CHUNK - 1;

    // Rows s_start .. s_last-1 from global; the final row comes from regs.
    for (int s = s_start; s <= s_last; ++s) {
        float4 cur[4];
        if (s < s_last) {
            const float4* row = base + (size_t)s * D4 + lane;
            #pragma unroll
            for (int j = 0; j < 4; ++j) cur[j] = row[32 * j];
        } else {
            #pragma unroll
            for (int j = 0; j < 4; ++j) cur[j] = last[j];
        }

        float sum = 0.0f;
        #pragma unroll
        for (int j = 0; j < 4; ++j) {
            float dx = cur[j].x - prev[j].x;
            float dy = cur[j].y - prev[j].y;
            float dz = cur[j].z - prev[j].z;
            float dw = cur[j].w - prev[j].w;
            sum += dx * dx + dy * dy + dz * dz + dw * dw;
        }
        // warp reduce (sum over D)
        #pragma unroll
        for (int off = 16; off > 0; off >>= 1)
            sum += __shfl_xor_sync(0xffffffffu, sum, off);
        if (lane == 0) orow[s] = sum;

        #pragma unroll
        for (int j = 0; j < 4; ++j) prev[j] = cur[j];
    }
}

// Kernel 2: fused max+scale, one block per batch, single pass (R5 version).
constexpr int NTHREADS2 = 512;                 // = S/4 float4 per row
constexpr int NWARPS2 = NTHREADS2 / 32;        // 16

__global__ void __launch_bounds__(NTHREADS2)
normalize_kernel(float4* __restrict__ out) {
    const int b = blockIdx.x;
    float4* row = out + (size_t)b * (S / 4);

    float4 v = row[threadIdx.x];
    float m = fmaxf(fmaxf(v.x, v.y), fmaxf(v.z, v.w));

    #pragma unroll
    for (int off = 16; off > 0; off >>= 1)
        m = fmaxf(m, __shfl_xor_sync(0xffffffffu, m, off));

    __shared__ float s_wmax[NWARPS2];
    __shared__ float s_inv;
    const int wid = threadIdx.x >> 5;
    const int lid = threadIdx.x & 31;
    if (lid == 0) s_wmax[wid] = m;
    __syncthreads();

    if (threadIdx.x < 32) {
        float t = (threadIdx.x < NWARPS2) ? s_wmax[threadIdx.x] : 0.0f;
        #pragma unroll
        for (int off = 8; off > 0; off >>= 1)
            t = fmaxf(t, __shfl_xor_sync(0xffffffffu, t, off));
        if (threadIdx.x == 0) s_inv = 1.0f / t;
    }
    __syncthreads();

    const float inv = s_inv;
    v.x *= inv; v.y *= inv; v.z *= inv; v.w *= inv;
    row[threadIdx.x] = v;
}

extern "C" void kernel_launch(void* const* d_in, const int* in_sizes, int n_in,
                              void* d_out, int out_size) {
    const float4* x = (const float4*)d_in[0];
    (void)in_sizes; (void)n_in; (void)out_size;

    l2_diff_kernel<<<GRID1, THREADS>>>(x, (float*)d_out);
    normalize_kernel<<<B, NTHREADS2>>>((float4*)d_out);
}

// round 8
// speedup vs baseline: 1.0417x; 1.0192x over previous
#include <cuda_runtime.h>

// Problem shape (fixed by reference setup_inputs): [B=64, S=2048, D=512] fp32
constexpr int B = 64;
constexpr int S = 2048;
constexpr int D = 512;
constexpr int D4 = D / 4;                      // 128 float4 per row
constexpr int CHUNK = 16;                      // timesteps per warp
constexpr int THREADS = 256;                   // 8 warps/block (measured best shape)
constexpr int WARPS_PER_BLOCK = THREADS / 32;  // 8
constexpr int ROWS_PER_BLOCK = WARPS_PER_BLOCK * CHUNK;       // 128
constexpr int BLOCKS_PER_BATCH = S / ROWS_PER_BLOCK;          // 16
constexpr int GRID1 = B * BLOCKS_PER_BATCH;                   // 1024 blocks

// Per-block max scratch: [B][BLOCKS_PER_BATCH]. Plain stores only (no atomics —
// R3/R4 showed a device-atomic tail costs ~9us). Rewritten identically on every
// graph replay (deterministic).
__device__ float g_blockmax[GRID1];

__device__ __forceinline__ float4 ldcs4(const float4* p) {
    return __ldcs(p);   // streaming: read-once data, don't fight for L2 residency
}

// Kernel 1: unnormalized squared L2 of consecutive-row diffs + per-block max.
// Block = 128 consecutive rows of one batch; warps share chunk-boundary rows via
// smem (re-read overhead 129/128).
__global__ void __launch_bounds__(THREADS)
l2_diff_kernel(const float4* __restrict__ x, float* __restrict__ out) {
    __shared__ float4 s_bound[WARPS_PER_BLOCK * 128];  // 8 rows x 512 floats = 16KB
    __shared__ float  s_wmax[WARPS_PER_BLOCK];

    const int b    = blockIdx.x / BLOCKS_PER_BATCH;
    const int r0   = (blockIdx.x % BLOCKS_PER_BATCH) * ROWS_PER_BLOCK;
    const int w    = threadIdx.x >> 5;
    const int lane = threadIdx.x & 31;
    const int s0   = r0 + w * CHUNK;

    const float4* base = x + (size_t)b * S * D4;
    float* orow = out + (size_t)b * S;

    // Phase 1: load my chunk's LAST row; share it with warp w+1 via smem.
    float4 last[4];
    {
        const float4* rl = base + (size_t)(s0 + CHUNK - 1) * D4 + lane;
        #pragma unroll
        for (int j = 0; j < 4; ++j) last[j] = ldcs4(rl + 32 * j);
        float4* sm = s_bound + w * 128 + lane;
        #pragma unroll
        for (int j = 0; j < 4; ++j) sm[32 * j] = last[j];
    }

    // Warp 0 also loads the block's global boundary row.
    float4 prev[4];
    const bool first_chunk = (r0 == 0) && (w == 0);
    if (w == 0) {
        const int sprev = (r0 == 0) ? 0 : (r0 - 1);
        const float4* rp = base + (size_t)sprev * D4 + lane;
        #pragma unroll
        for (int j = 0; j < 4; ++j) prev[j] = ldcs4(rp + 32 * j);
    }

    __syncthreads();

    if (w != 0) {
        const float4* sp = s_bound + (w - 1) * 128 + lane;
        #pragma unroll
        for (int j = 0; j < 4; ++j) prev[j] = sp[32 * j];
    }

    if (first_chunk && lane == 0) orow[0] = 0.0f;

    const int s_start = first_chunk ? 1 : s0;
    const int s_last  = s0 + CHUNK - 1;

    float wmax = 0.0f;  // d >= 0 everywhere (and d[0] = 0)

    for (int s = s_start; s <= s_last; ++s) {
        float4 cur[4];
        if (s < s_last) {
            const float4* row = base + (size_t)s * D4 + lane;
            #pragma unroll
            for (int j = 0; j < 4; ++j) cur[j] = ldcs4(row + 32 * j);
        } else {
            #pragma unroll
            for (int j = 0; j < 4; ++j) cur[j] = last[j];
        }

        float sum = 0.0f;
        #pragma unroll
        for (int j = 0; j < 4; ++j) {
            float dx = cur[j].x - prev[j].x;
            float dy = cur[j].y - prev[j].y;
            float dz = cur[j].z - prev[j].z;
            float dw = cur[j].w - prev[j].w;
            sum += dx * dx + dy * dy + dz * dz + dw * dw;
        }
        // warp reduce (sum over D); all lanes end with the full sum
        #pragma unroll
        for (int off = 16; off > 0; off >>= 1)
            sum += __shfl_xor_sync(0xffffffffu, sum, off);
        wmax = fmaxf(wmax, sum);
        if (lane == 0) orow[s] = sum;

        #pragma unroll
        for (int j = 0; j < 4; ++j) prev[j] = cur[j];
    }

    // Block max -> plain store (NOT atomic).
    if (lane == 0) s_wmax[w] = wmax;
    __syncthreads();
    if (threadIdx.x == 0) {
        float m = s_wmax[0];
        #pragma unroll
        for (int i = 1; i < WARPS_PER_BLOCK; ++i) m = fmaxf(m, s_wmax[i]);
        g_blockmax[blockIdx.x] = m;
    }
}

// Kernel 2: near-elementwise normalize. 256 blocks x 256 threads; each block
// covers 1/4 of one batch (whole block shares one b). Every warp redundantly
// reduces the batch's 16 block-maxes via shuffles — no smem, no __syncthreads.
constexpr int NTHREADS2 = 256;
constexpr int F2_PER_BATCH = S / 2;                     // 1024
constexpr int GRID2 = (B * S / 2) / NTHREADS2;          // 256 blocks

__global__ void __launch_bounds__(NTHREADS2)
normalize_kernel(float2* __restrict__ out) {
    const int i = blockIdx.x * NTHREADS2 + threadIdx.x;  // float2 index
    const int b = blockIdx.x / (F2_PER_BATCH / NTHREADS2);  // 4 blocks per batch

    const int lane = threadIdx.x & 31;
    float m = g_blockmax[b * BLOCKS_PER_BATCH + (lane & 15)];
    #pragma unroll
    for (int off = 8; off > 0; off >>= 1)
        m = fmaxf(m, __shfl_xor_sync(0xffffffffu, m, off));
    const float inv = 1.0f / m;

    float2 v = out[i];
    v.x *= inv; v.y *= inv;
    out[i] = v;
}

extern "C" void kernel_launch(void* const* d_in, const int* in_sizes, int n_in,
                              void* d_out, int out_size) {
    const float4* x = (const float4*)d_in[0];
    (void)in_sizes; (void)n_in; (void)out_size;

    l2_diff_kernel<<<GRID1, THREADS>>>(x, (float*)d_out);
    normalize_kernel<<<GRID2, NTHREADS2>>>((float2*)d_out);
}